// round 10
// baseline (speedup 1.0000x reference)
#include <cuda_runtime.h>
#include <cuda_bf16.h>
#include <math_constants.h>
#include <cstdint>

// ---------------------------------------------------------------------------
// MHA Round 10: GEMM 3-stage pipeline (72KB dyn smem, fallback to 2-stage if
// the smem attribute is refused); attention double-buffers K by reusing the
// Q smem after Q-fragments are register resident (stays 48KB static, occ 3).
// ---------------------------------------------------------------------------

#define B_      2
#define S_      2048
#define HID     1024
#define HEADS   16
#define HD      64
#define M_TOT   (B_ * S_)
#define SCALE   0.125f
#define K3      3072

__device__ __nv_bfloat16 g_Xe[M_TOT * K3];
__device__ __nv_bfloat16 g_We[3 * HID * K3];
__device__ __nv_bfloat16 g_Ue[HID * K3];
__device__ __nv_bfloat16 g_Oe[M_TOT * K3];

__device__ __nv_bfloat16 g_Qh[B_ * HEADS * S_ * HD];
__device__ __nv_bfloat16 g_Ql[B_ * HEADS * S_ * HD];
__device__ __nv_bfloat16 g_Kh[B_ * HEADS * S_ * HD];
__device__ __nv_bfloat16 g_Kl[B_ * HEADS * S_ * HD];
__device__ __nv_bfloat16 g_Vth[B_ * HEADS * HD * S_];
__device__ __nv_bfloat16 g_Vtl[B_ * HEADS * HD * S_];

// ---------------------------------------------------------------------------
__device__ __forceinline__ uint32_t smem_u32(const void* p) {
    uint32_t a;
    asm("{ .reg .u64 t; cvta.to.shared.u64 t, %1; cvt.u32.u64 %0, t; }"
        : "=r"(a) : "l"(p));
    return a;
}
__device__ __forceinline__ void ldsm_x4(uint32_t* r, uint32_t addr) {
    asm volatile("ldmatrix.sync.aligned.m8n8.x4.shared.b16 {%0,%1,%2,%3}, [%4];"
        : "=r"(r[0]), "=r"(r[1]), "=r"(r[2]), "=r"(r[3]) : "r"(addr));
}
__device__ __forceinline__ void mma16816(float* d, const uint32_t* a,
                                         uint32_t b0, uint32_t b1) {
    asm volatile(
        "mma.sync.aligned.m16n8k16.row.col.f32.bf16.bf16.f32 "
        "{%0,%1,%2,%3}, {%4,%5,%6,%7}, {%8,%9}, {%0,%1,%2,%3};"
        : "+f"(d[0]), "+f"(d[1]), "+f"(d[2]), "+f"(d[3])
        : "r"(a[0]), "r"(a[1]), "r"(a[2]), "r"(a[3]), "r"(b0), "r"(b1));
}
__device__ __forceinline__ uint32_t sw(uint32_t off) {
    return off ^ ((off >> 3) & 0x70);
}
__device__ __forceinline__ uint32_t pack_bf16(float lo, float hi) {
    __nv_bfloat162 t = __floats2bfloat162_rn(lo, hi);
    return *reinterpret_cast<uint32_t*>(&t);
}
__device__ __forceinline__ void cp16(uint32_t saddr, const void* g) {
    asm volatile("cp.async.cg.shared.global [%0], [%1], 16;"
                 :: "r"(saddr), "l"(g) : "memory");
}
#define CP_COMMIT() asm volatile("cp.async.commit_group;" ::: "memory")
template <int N>
__device__ __forceinline__ void cp_wait() {
    asm volatile("cp.async.wait_group %0;" :: "n"(N) : "memory");
}

// ---------------------------------------------------------------------------
// merged extended-K converter
// ---------------------------------------------------------------------------
#define NX (M_TOT * HID)
#define NW (3 * HID * HID)
#define NU (HID * HID)

__global__ void convert_all(const float* __restrict__ x,
                            const float* __restrict__ wqkv,
                            const float* __restrict__ wout)
{
    const int ntot = NX + NW + NU;
    for (int i = blockIdx.x * blockDim.x + threadIdx.x; i < ntot;
         i += gridDim.x * blockDim.x) {
        const float* src;
        __nv_bfloat16* dst;
        int j, apat;
        if (i < NX)           { src = x;    dst = g_Xe; j = i;           apat = 1; }
        else if (i < NX + NW) { src = wqkv; dst = g_We; j = i - NX;      apat = 0; }
        else                  { src = wout; dst = g_Ue; j = i - NX - NW; apat = 0; }
        int m = j >> 10;
        int k = j & 1023;
        float xv = src[j];
        __nv_bfloat16 h = __float2bfloat16(xv);
        __nv_bfloat16 l = __float2bfloat16(xv - __bfloat162float(h));
        size_t base = (size_t)m * K3 + k;
        dst[base] = h;
        if (apat) { dst[base + 1024] = h; dst[base + 2048] = l; }
        else      { dst[base + 1024] = l; dst[base + 2048] = h; }
    }
}

// ---------------------------------------------------------------------------
// shared GEMM epilogue (CTA 128x64, warps 4Mx2N, warp tile 32x32)
// ---------------------------------------------------------------------------
template <int MODE>
__device__ __forceinline__ void gemm_epilogue(float acc[2][4][4],
                                              float* __restrict__ Cout,
                                              int bm, int bn, int wm, int wn,
                                              int lid)
{
    const int tg = lid >> 2;
    const int tc = (lid & 3) * 2;

    if (MODE == 1) {
#pragma unroll
        for (int mi = 0; mi < 2; mi++)
#pragma unroll
            for (int ni = 0; ni < 4; ni++) {
                int m0 = bm * 128 + wm * 32 + mi * 16 + tg;
                int n0 = bn * 64 + wn * 32 + ni * 8 + tc;
                *reinterpret_cast<float2*>(&Cout[(size_t)m0 * HID + n0]) =
                    make_float2(acc[mi][ni][0], acc[mi][ni][1]);
                *reinterpret_cast<float2*>(&Cout[(size_t)(m0 + 8) * HID + n0]) =
                    make_float2(acc[mi][ni][2], acc[mi][ni][3]);
            }
    } else {
#pragma unroll
        for (int mi = 0; mi < 2; mi++)
#pragma unroll
            for (int ni = 0; ni < 4; ni++)
#pragma unroll
                for (int q = 0; q < 4; q++) {
                    int m = bm * 128 + wm * 32 + mi * 16 + tg + (q >> 1) * 8;
                    int e = bn * 64 + wn * 32 + ni * 8 + tc + (q & 1);
                    float val = acc[mi][ni][q];
                    int b = m >> 11, s = m & 2047;
                    int region = e >> 10;
                    int e2 = e & 1023;
                    int h = e2 >> 6, d = e2 & 63;
                    int bh = b * HEADS + h;
                    if (region == 0) {
                        float qv = val * SCALE;
                        __nv_bfloat16 hv = __float2bfloat16(qv);
                        size_t off = ((size_t)bh * S_ + s) * HD + d;
                        g_Qh[off] = hv;
                        g_Ql[off] = __float2bfloat16(qv - __bfloat162float(hv));
                    } else if (region == 1) {
                        __nv_bfloat16 hv = __float2bfloat16(val);
                        size_t off = ((size_t)bh * S_ + s) * HD + d;
                        g_Kh[off] = hv;
                        g_Kl[off] = __float2bfloat16(val - __bfloat162float(hv));
                    } else {
                        __nv_bfloat16 hv = __float2bfloat16(val);
                        size_t off = ((size_t)bh * HD + d) * S_ + s;
                        g_Vth[off] = hv;
                        g_Vtl[off] = __float2bfloat16(val - __bfloat162float(hv));
                    }
                }
    }
}

#define NKT (K3 / 64)    // 48

// ---------------------------------------------------------------------------
// 3-stage GEMM, 72KB dynamic smem (+1KB align slack)
// ---------------------------------------------------------------------------
#define GEMM3_BYTES (3 * 24576 + 1024)

template <int MODE>
__global__ __launch_bounds__(256, 2) void mma_gemm3(float* __restrict__ Cout)
{
    extern __shared__ char dsm[];
    const uint32_t sbase  = smem_u32(dsm);
    const uint32_t base1k = (sbase + 1023u) & ~1023u;

    const int tid = threadIdx.x;
    const int wid = tid >> 5;
    const int lid = tid & 31;
    const int bn = blockIdx.x;
    const int bm = blockIdx.y;
    const int wm = wid & 3;
    const int wn = wid >> 2;

    const __nv_bfloat16* Ag = (MODE == 0) ? g_Xe : g_Oe;
    const __nv_bfloat16* Bg = (MODE == 0) ? g_We : g_Ue;

    uint32_t aA[3], aB[3];
#pragma unroll
    for (int s = 0; s < 3; s++) {
        aA[s] = base1k + s * 24576;
        aB[s] = base1k + s * 24576 + 16384;
    }

    auto issue_stage = [&](int kt, int s) {
#pragma unroll
        for (int p = 0; p < 4; p++) {
            int idx = tid + p * 256;
            int r = idx >> 3, j = idx & 7;
            cp16(aA[s] + sw((uint32_t)(r * 128 + j * 16)),
                 Ag + (size_t)(bm * 128 + r) * K3 + kt * 64 + j * 8);
        }
#pragma unroll
        for (int p = 0; p < 2; p++) {
            int idx = tid + p * 256;
            int r = idx >> 3, j = idx & 7;
            cp16(aB[s] + sw((uint32_t)(r * 128 + j * 16)),
                 Bg + (size_t)(bn * 64 + r) * K3 + kt * 64 + j * 8);
        }
    };

    float acc[2][4][4];
#pragma unroll
    for (int a = 0; a < 2; a++)
#pragma unroll
        for (int b = 0; b < 4; b++)
#pragma unroll
            for (int c = 0; c < 4; c++) acc[a][b][c] = 0.f;

    const int lrow = lid & 15;
    const int lkb  = lid >> 4;

    issue_stage(0, 0); CP_COMMIT();
    issue_stage(1, 1); CP_COMMIT();
    issue_stage(2, 2); CP_COMMIT();

    for (int kt = 0; kt < NKT; kt++) {
        cp_wait<2>();
        __syncthreads();

        const int st = kt % 3;
        const uint32_t cA = aA[st], cB = aB[st];

#pragma unroll
        for (int ks = 0; ks < 4; ks++) {
            uint32_t afr[2][4], bfr[2][4];
#pragma unroll
            for (int mi = 0; mi < 2; mi++) {
                uint32_t o = (uint32_t)((wm * 32 + mi * 16 + lrow) * 128 +
                                        ks * 32 + lkb * 16);
                ldsm_x4(afr[mi], cA + sw(o));
            }
#pragma unroll
            for (int nb = 0; nb < 2; nb++) {
                uint32_t o = (uint32_t)((wn * 32 + nb * 16 + lrow) * 128 +
                                        ks * 32 + lkb * 16);
                ldsm_x4(bfr[nb], cB + sw(o));
            }
#pragma unroll
            for (int mi = 0; mi < 2; mi++)
#pragma unroll
                for (int ni = 0; ni < 4; ni++)
                    mma16816(acc[mi][ni], afr[mi],
                             bfr[ni >> 1][ni & 1], bfr[ni >> 1][(ni & 1) + 2]);
        }

        __syncthreads();
        if (kt + 3 < NKT) issue_stage(kt + 3, st);
        CP_COMMIT();
    }

    gemm_epilogue<MODE>(acc, Cout, bm, bn, wm, wn, lid);
}

// ---------------------------------------------------------------------------
// 2-stage GEMM, 48KB static (R9 fallback, proven)
// ---------------------------------------------------------------------------
template <int MODE>
__global__ __launch_bounds__(256, 2) void mma_gemm2(float* __restrict__ Cout)
{
    __shared__ __align__(128) __nv_bfloat16 sA[2][128 * 64];
    __shared__ __align__(128) __nv_bfloat16 sB[2][64 * 64];

    const int tid = threadIdx.x;
    const int wid = tid >> 5;
    const int lid = tid & 31;
    const int bn = blockIdx.x;
    const int bm = blockIdx.y;
    const int wm = wid & 3;
    const int wn = wid >> 2;

    const __nv_bfloat16* Ag = (MODE == 0) ? g_Xe : g_Oe;
    const __nv_bfloat16* Bg = (MODE == 0) ? g_We : g_Ue;

    const uint32_t aA0 = smem_u32(sA[0]);
    const uint32_t aA1 = smem_u32(sA[1]);
    const uint32_t aB0 = smem_u32(sB[0]);
    const uint32_t aB1 = smem_u32(sB[1]);

    auto issue_stage = [&](int kt, int buf) {
        const uint32_t dA = buf ? aA1 : aA0;
        const uint32_t dB = buf ? aB1 : aB0;
#pragma unroll
        for (int p = 0; p < 4; p++) {
            int idx = tid + p * 256;
            int r = idx >> 3, j = idx & 7;
            cp16(dA + sw((uint32_t)(r * 128 + j * 16)),
                 Ag + (size_t)(bm * 128 + r) * K3 + kt * 64 + j * 8);
        }
#pragma unroll
        for (int p = 0; p < 2; p++) {
            int idx = tid + p * 256;
            int r = idx >> 3, j = idx & 7;
            cp16(dB + sw((uint32_t)(r * 128 + j * 16)),
                 Bg + (size_t)(bn * 64 + r) * K3 + kt * 64 + j * 8);
        }
    };

    float acc[2][4][4];
#pragma unroll
    for (int a = 0; a < 2; a++)
#pragma unroll
        for (int b = 0; b < 4; b++)
#pragma unroll
            for (int c = 0; c < 4; c++) acc[a][b][c] = 0.f;

    const int lrow = lid & 15;
    const int lkb  = lid >> 4;

    issue_stage(0, 0); CP_COMMIT();
    issue_stage(1, 1); CP_COMMIT();

    for (int kt = 0; kt < NKT; kt++) {
        cp_wait<1>();
        __syncthreads();

        const uint32_t cA = (kt & 1) ? aA1 : aA0;
        const uint32_t cB = (kt & 1) ? aB1 : aB0;

#pragma unroll
        for (int ks = 0; ks < 4; ks++) {
            uint32_t afr[2][4], bfr[2][4];
#pragma unroll
            for (int mi = 0; mi < 2; mi++) {
                uint32_t o = (uint32_t)((wm * 32 + mi * 16 + lrow) * 128 +
                                        ks * 32 + lkb * 16);
                ldsm_x4(afr[mi], cA + sw(o));
            }
#pragma unroll
            for (int nb = 0; nb < 2; nb++) {
                uint32_t o = (uint32_t)((wn * 32 + nb * 16 + lrow) * 128 +
                                        ks * 32 + lkb * 16);
                ldsm_x4(bfr[nb], cB + sw(o));
            }
#pragma unroll
            for (int mi = 0; mi < 2; mi++)
#pragma unroll
                for (int ni = 0; ni < 4; ni++)
                    mma16816(acc[mi][ni], afr[mi],
                             bfr[ni >> 1][ni & 1], bfr[ni >> 1][(ni & 1) + 2]);
        }

        __syncthreads();
        if (kt + 2 < NKT) issue_stage(kt + 2, kt & 1);
        CP_COMMIT();
    }

    gemm_epilogue<MODE>(acc, Cout, bm, bn, wm, wn, lid);
}

// ---------------------------------------------------------------------------
// Attention: 3-term hi/lo bf16, double-buffered K (Q smem reused as K stage 1
// after Q fragments are register resident). 48KB static, occ 3.
// Commit order: g0=[Q,K0], g1=[V0], g2=[K1], per-iter: gA=[K(kt+2)], gB=[V(kt+1)]
// top wait<=2  -> K(kt) ready;  mid wait<=1 -> V(kt) ready.
// ---------------------------------------------------------------------------
__device__ __forceinline__ void cp_tile64(uint32_t sdst,
                                          const __nv_bfloat16* g,
                                          int gstride, int tid)
{
#pragma unroll
    for (int p = 0; p < 4; p++) {
        int idx = tid + p * 128;
        int r = idx >> 3, j = idx & 7;
        cp16(sdst + sw((uint32_t)(r * 128 + j * 16)),
             g + (size_t)r * gstride + j * 8);
    }
}

__global__ __launch_bounds__(128, 3) void attn_mma()
{
    __shared__ __align__(128) __nv_bfloat16 sQh[4096], sQl[4096];  // -> K stage 1
    __shared__ __align__(128) __nv_bfloat16 sKh[4096], sKl[4096];  // K stage 0
    __shared__ __align__(128) __nv_bfloat16 sVh[4096], sVl[4096];

    const int tid = threadIdx.x;
    const int wid = tid >> 5;
    const int lid = tid & 31;
    const int qt = blockIdx.x;
    const int bh = blockIdx.y;
    const int b  = bh >> 4;
    const int h  = bh & 15;

    const int lrow = lid & 15;
    const int lkb  = lid >> 4;
    const int tg   = lid >> 2;
    const int tc   = (lid & 3) * 2;

    const uint32_t aQh = smem_u32(sQh), aQl = smem_u32(sQl);
    const uint32_t aKh = smem_u32(sKh), aKl = smem_u32(sKl);
    const uint32_t aVh = smem_u32(sVh), aVl = smem_u32(sVl);

    const __nv_bfloat16* Kh = g_Kh + (size_t)bh * S_ * HD;
    const __nv_bfloat16* Kl = g_Kl + (size_t)bh * S_ * HD;
    const __nv_bfloat16* Vh = g_Vth + (size_t)bh * HD * S_;
    const __nv_bfloat16* Vl = g_Vtl + (size_t)bh * HD * S_;

    const int NT = S_ / 64;

    // prologue
    const size_t qoff = ((size_t)bh * S_ + qt * 64) * HD;
    cp_tile64(aQh, g_Qh + qoff, HD, tid);
    cp_tile64(aQl, g_Ql + qoff, HD, tid);
    cp_tile64(aKh, Kh, HD, tid);
    cp_tile64(aKl, Kl, HD, tid);
    CP_COMMIT();                                  // g0 = [Q, K0]
    cp_tile64(aVh, Vh, S_, tid);
    cp_tile64(aVl, Vl, S_, tid);
    CP_COMMIT();                                  // g1 = [V0]

    cp_wait<1>();                                 // g0 done
    __syncthreads();

    uint32_t qfh[4][4], qfl[4][4];
#pragma unroll
    for (int ks = 0; ks < 4; ks++) {
        uint32_t o = (uint32_t)((wid * 16 + lrow) * 128 + ks * 32 + lkb * 16);
        ldsm_x4(qfh[ks], aQh + sw(o));
        ldsm_x4(qfl[ks], aQl + sw(o));
    }
    __syncthreads();                              // all warps done reading Q
    if (NT > 1) {
        cp_tile64(aQh, Kh + (size_t)64 * HD, HD, tid);
        cp_tile64(aQl, Kl + (size_t)64 * HD, HD, tid);
    }
    CP_COMMIT();                                  // g2 = [K1] (into Q bufs)

    float oacc[8][4];
#pragma unroll
    for (int t = 0; t < 8; t++)
#pragma unroll
        for (int c = 0; c < 4; c++) oacc[t][c] = 0.f;
    float m0 = -CUDART_INF_F, m1 = -CUDART_INF_F;
    float l0 = 0.f, l1 = 0.f;

    for (int kt = 0; kt < NT; kt++) {
        cp_wait<2>();                 // K(kt) ready
        __syncthreads();

        const uint32_t ckh = (kt & 1) ? aQh : aKh;
        const uint32_t ckl = (kt & 1) ? aQl : aKl;

        // ---- S = Q K^T, 3-term ----
        float sacc[8][4];
#pragma unroll
        for (int t = 0; t < 8; t++)
#pragma unroll
            for (int c = 0; c < 4; c++) sacc[t][c] = 0.f;

#pragma unroll
        for (int ks = 0; ks < 4; ks++) {
            uint32_t kbh[4][4], kbl[4][4];
#pragma unroll
            for (int nb = 0; nb < 4; nb++) {
                uint32_t o = (uint32_t)((nb * 16 + lrow) * 128 + ks * 32 + lkb * 16);
                ldsm_x4(kbh[nb], ckh + sw(o));
                ldsm_x4(kbl[nb], ckl + sw(o));
            }
#pragma unroll
            for (int nt = 0; nt < 8; nt++) {
                uint32_t bh0 = kbh[nt >> 1][nt & 1], bh1 = kbh[nt >> 1][(nt & 1) + 2];
                uint32_t bl0 = kbl[nt >> 1][nt & 1], bl1 = kbl[nt >> 1][(nt & 1) + 2];
                mma16816(sacc[nt], qfh[ks], bh0, bh1);
                mma16816(sacc[nt], qfh[ks], bl0, bl1);
                mma16816(sacc[nt], qfl[ks], bh0, bh1);
            }
        }

        __syncthreads();              // K buffer free to overwrite
        if (kt + 2 < NT) {
            cp_tile64(ckh, Kh + (size_t)(kt + 2) * 64 * HD, HD, tid);
            cp_tile64(ckl, Kl + (size_t)(kt + 2) * 64 * HD, HD, tid);
        }
        CP_COMMIT();                  // gA_kt

        // ---- online softmax ----
        float rm0 = -CUDART_INF_F, rm1 = -CUDART_INF_F;
#pragma unroll
        for (int t = 0; t < 8; t++) {
            rm0 = fmaxf(rm0, fmaxf(sacc[t][0], sacc[t][1]));
            rm1 = fmaxf(rm1, fmaxf(sacc[t][2], sacc[t][3]));
        }
        rm0 = fmaxf(rm0, __shfl_xor_sync(0xffffffffu, rm0, 1));
        rm0 = fmaxf(rm0, __shfl_xor_sync(0xffffffffu, rm0, 2));
        rm1 = fmaxf(rm1, __shfl_xor_sync(0xffffffffu, rm1, 1));
        rm1 = fmaxf(rm1, __shfl_xor_sync(0xffffffffu, rm1, 2));

        float mn0 = fmaxf(m0, rm0), mn1 = fmaxf(m1, rm1);
        float cr0 = __expf(m0 - mn0), cr1 = __expf(m1 - mn1);
        m0 = mn0; m1 = mn1;

        float rs0 = 0.f, rs1 = 0.f;
#pragma unroll
        for (int t = 0; t < 8; t++) {
            sacc[t][0] = __expf(sacc[t][0] - mn0);
            sacc[t][1] = __expf(sacc[t][1] - mn0);
            sacc[t][2] = __expf(sacc[t][2] - mn1);
            sacc[t][3] = __expf(sacc[t][3] - mn1);
            rs0 += sacc[t][0] + sacc[t][1];
            rs1 += sacc[t][2] + sacc[t][3];
        }
        rs0 += __shfl_xor_sync(0xffffffffu, rs0, 1);
        rs0 += __shfl_xor_sync(0xffffffffu, rs0, 2);
        rs1 += __shfl_xor_sync(0xffffffffu, rs1, 1);
        rs1 += __shfl_xor_sync(0xffffffffu, rs1, 2);
        l0 = l0 * cr0 + rs0;
        l1 = l1 * cr1 + rs1;

#pragma unroll
        for (int t = 0; t < 8; t++) {
            oacc[t][0] *= cr0; oacc[t][1] *= cr0;
            oacc[t][2] *= cr1; oacc[t][3] *= cr1;
        }

        // ---- pack P (hi/lo) ----
        uint32_t pah[4][4], pal[4][4];
#pragma unroll
        for (int ks = 0; ks < 4; ks++) {
            const int t0 = 2 * ks, t1 = 2 * ks + 1;
            float ph[8], pl[8];
            const float pv[8] = {sacc[t0][0], sacc[t0][1], sacc[t0][2], sacc[t0][3],
                                 sacc[t1][0], sacc[t1][1], sacc[t1][2], sacc[t1][3]};
#pragma unroll
            for (int e = 0; e < 8; e++) {
                __nv_bfloat16 hb = __float2bfloat16(pv[e]);
                ph[e] = __bfloat162float(hb);
                pl[e] = pv[e] - ph[e];
            }
            pah[ks][0] = pack_bf16(ph[0], ph[1]);
            pah[ks][1] = pack_bf16(ph[2], ph[3]);
            pah[ks][2] = pack_bf16(ph[4], ph[5]);
            pah[ks][3] = pack_bf16(ph[6], ph[7]);
            pal[ks][0] = pack_bf16(pl[0], pl[1]);
            pal[ks][1] = pack_bf16(pl[2], pl[3]);
            pal[ks][2] = pack_bf16(pl[4], pl[5]);
            pal[ks][3] = pack_bf16(pl[6], pl[7]);
        }

        cp_wait<1>();                 // V(kt) ready
        __syncthreads();

        // ---- O += P V, 3-term ----
#pragma unroll
        for (int ks = 0; ks < 4; ks++) {
            uint32_t vbh[4][4], vbl[4][4];
#pragma unroll
            for (int nb = 0; nb < 4; nb++) {
                uint32_t o = (uint32_t)((nb * 16 + lrow) * 128 + ks * 32 + lkb * 16);
                ldsm_x4(vbh[nb], aVh + sw(o));
                ldsm_x4(vbl[nb], aVl + sw(o));
            }
#pragma unroll
            for (int nt = 0; nt < 8; nt++) {
                uint32_t bh0 = vbh[nt >> 1][nt & 1], bh1 = vbh[nt >> 1][(nt & 1) + 2];
                uint32_t bl0 = vbl[nt >> 1][nt & 1], bl1 = vbl[nt >> 1][(nt & 1) + 2];
                mma16816(oacc[nt], pah[ks], bh0, bh1);
                mma16816(oacc[nt], pah[ks], bl0, bl1);
                mma16816(oacc[nt], pal[ks], bh0, bh1);
            }
        }

        __syncthreads();              // V buffer free to overwrite
        if (kt + 1 < NT) {
            cp_tile64(aVh, Vh + (size_t)(kt + 1) * 64, S_, tid);
            cp_tile64(aVl, Vl + (size_t)(kt + 1) * 64, S_, tid);
        }
        CP_COMMIT();                  // gB_kt
    }

    // ---- epilogue: write g_Oe (extended-K A-pattern [hi|hi|lo]) ----
    const float inv0 = 1.f / l0, inv1 = 1.f / l1;
    const int r0 = qt * 64 + wid * 16 + tg;
    const int m0row = b * S_ + r0;
#pragma unroll
    for (int nt = 0; nt < 8; nt++) {
        int col = h * 64 + nt * 8 + tc;
#pragma unroll
        for (int q = 0; q < 4; q++) {
            int m = m0row + (q >> 1) * 8;
            int k = col + (q & 1);
            float val = oacc[nt][q] * ((q < 2) ? inv0 : inv1);
            __nv_bfloat16 hv = __float2bfloat16(val);
            size_t base = (size_t)m * K3 + k;
            g_Oe[base]        = hv;
            g_Oe[base + 1024] = hv;
            g_Oe[base + 2048] = __float2bfloat16(val - __bfloat162float(hv));
        }
    }
}

// ---------------------------------------------------------------------------
extern "C" void kernel_launch(void* const* d_in, const int* in_sizes, int n_in,
                              void* d_out, int out_size)
{
    const float* x    = (const float*)d_in[0];
    const float* wqkv = (const float*)d_in[1];
    const float* wout = (const float*)d_in[2];
    for (int i = 0; i < n_in; i++) {
        if      (in_sizes[i] == 4194304) x    = (const float*)d_in[i];
        else if (in_sizes[i] == 3145728) wqkv = (const float*)d_in[i];
        else if (in_sizes[i] == 1048576) wout = (const float*)d_in[i];
    }
    float* out = (float*)d_out;

    // opt in to 72KB dynamic smem for the 3-stage GEMM; fall back if refused
    bool g3 = true;
    if (cudaFuncSetAttribute(mma_gemm3<0>,
            cudaFuncAttributeMaxDynamicSharedMemorySize, GEMM3_BYTES)
        != cudaSuccess) g3 = false;
    if (g3 && cudaFuncSetAttribute(mma_gemm3<1>,
            cudaFuncAttributeMaxDynamicSharedMemorySize, GEMM3_BYTES)
        != cudaSuccess) g3 = false;
    (void)cudaGetLastError();   // clear any sticky error from a refused attr

    convert_all<<<2048, 256>>>(x, wqkv, wout);

    if (g3)
        mma_gemm3<0><<<dim3(3 * HID / 64, M_TOT / 128), 256, GEMM3_BYTES>>>(nullptr);
    else
        mma_gemm2<0><<<dim3(3 * HID / 64, M_TOT / 128), 256>>>(nullptr);

    attn_mma<<<dim3(S_ / 64, B_ * HEADS), 128>>>();

    if (g3)
        mma_gemm3<1><<<dim3(HID / 64, M_TOT / 128), 256, GEMM3_BYTES>>>(out);
    else
        mma_gemm2<1><<<dim3(HID / 64, M_TOT / 128), 256>>>(out);
}